// round 6
// baseline (speedup 1.0000x reference)
#include <cuda_runtime.h>
#include <math.h>

#define BATCH 16
#define DIM   512
#define S     128
#define PLANE (S*S)
#define PLANE4 (PLANE/4)
#define CSPLIT 4
#define CPER  (DIM/CSPLIT)     // 128 channels per split

// Accumulator for fused strip-conv partials:
// g_TR[b][0..4][w]   = T[kw][w']  (ww branch, pre-halo)
// g_TR[b][5..9][h]   = R[kh][h']  (hw branch, pre-halo)
// Invariant: zero on entry to kernel_launch (zero-initialized at module load,
// re-zeroed by k_tail after each use) -> no memset launch needed.
__device__ float g_TR[BATCH * 10 * S];

// ---------------------------------------------------------------------------
// K1: 1x1 conv 512->2 fused with strip-conv partial reductions.
// Block = 128 threads = 32 pixel4 (one image row) x 4 channel-splits.
// Grid = 2048 (16 b x 128 rows). No x2 ever written to DRAM.
// ---------------------------------------------------------------------------
__global__ void __launch_bounds__(128) k_conv_fused(const float* __restrict__ x,
                                                    const float* __restrict__ wconv,
                                                    const float* __restrict__ w_ww,
                                                    const float* __restrict__ w_hw) {
    __shared__ float2 s_wc[DIM];            // 4 KB
    __shared__ float4 red0[CSPLIT][32];     // 2 KB
    __shared__ float4 red1[CSPLIT][32];     // 2 KB
    __shared__ float  s_T[2][5][S];         // 5 KB (per input channel, no atomics)

    int tid = threadIdx.x;
    for (int c = tid; c < DIM; c += 128)
        s_wc[c] = make_float2(wconv[c], wconv[DIM + c]);
    __syncthreads();

    int s = tid >> 5;                  // channel split 0..3
    int p = tid & 31;                  // pixel4 within row
    int b  = blockIdx.x >> 7;          // batch
    int rb = blockIdx.x & 127;         // row index

    const float4* xb = reinterpret_cast<const float4*>(x)
                     + (size_t)b * DIM * PLANE4
                     + (size_t)s * CPER * PLANE4
                     + (size_t)rb * 32 + p;

    float4 a0 = make_float4(0.f, 0.f, 0.f, 0.f);
    float4 a1 = make_float4(0.f, 0.f, 0.f, 0.f);

    for (int c0 = 0; c0 < CPER; c0 += 8) {
        float4 v[8];
#pragma unroll
        for (int j = 0; j < 8; j++)
            v[j] = xb[(size_t)(c0 + j) * PLANE4];
#pragma unroll
        for (int j = 0; j < 8; j++) {
            float2 wc = s_wc[s * CPER + c0 + j];
            a0.x = fmaf(v[j].x, wc.x, a0.x); a0.y = fmaf(v[j].y, wc.x, a0.y);
            a0.z = fmaf(v[j].z, wc.x, a0.z); a0.w = fmaf(v[j].w, wc.x, a0.w);
            a1.x = fmaf(v[j].x, wc.y, a1.x); a1.y = fmaf(v[j].y, wc.y, a1.y);
            a1.z = fmaf(v[j].z, wc.y, a1.z); a1.w = fmaf(v[j].w, wc.y, a1.w);
        }
    }

    red0[s][p] = a0;
    red1[s][p] = a1;
    __syncthreads();

    // Threads 0..63: combine splits -> final x2 row values, emit partials.
    // ch = tid>>5 (0/1), pp = tid&31; each thread owns w = 4*pp..4*pp+3.
    if (tid < 64) {
        int ch = tid >> 5;
        int pp = tid & 31;
        float4 r;
        {
            float4 q0, q1, q2, q3;
            if (ch == 0) { q0 = red0[0][pp]; q1 = red0[1][pp]; q2 = red0[2][pp]; q3 = red0[3][pp]; }
            else         { q0 = red1[0][pp]; q1 = red1[1][pp]; q2 = red1[2][pp]; q3 = red1[3][pp]; }
            r = make_float4(q0.x + q1.x + q2.x + q3.x, q0.y + q1.y + q2.y + q3.y,
                            q0.z + q1.z + q2.z + q3.z, q0.w + q1.w + q2.w + q3.w);
        }
        int w0 = pp * 4;

        // T[ch][kw][w'] = x2[ch, rb, w'] * w_ww[ch, rb, kw]   (w_ww: [2,128,5])
#pragma unroll
        for (int kw = 0; kw < 5; kw++) {
            float wt = __ldg(&w_ww[(ch * S + rb) * 5 + kw]);
            s_T[ch][kw][w0 + 0] = r.x * wt;
            s_T[ch][kw][w0 + 1] = r.y * wt;
            s_T[ch][kw][w0 + 2] = r.z * wt;
            s_T[ch][kw][w0 + 3] = r.w * wt;
        }

        // R[kh][rb] += sum_w x2[ch, rb, w] * w_hw[ch, kh, w]   (w_hw: [2,5,128])
#pragma unroll
        for (int kh = 0; kh < 5; kh++) {
            const float* whp = w_hw + (ch * 5 + kh) * S + w0;
            float pr = r.x * __ldg(whp) + r.y * __ldg(whp + 1)
                     + r.z * __ldg(whp + 2) + r.w * __ldg(whp + 3);
#pragma unroll
            for (int off = 16; off > 0; off >>= 1)
                pr += __shfl_down_sync(0xFFFFFFFFu, pr, off);
            if (pp == 0)
                atomicAdd(&g_TR[b * (10 * S) + (5 + kh) * S + rb], pr);
        }
    }
    __syncthreads();

    // Flush block-local T (both channels combined) to global accumulator
    for (int k = tid; k < 5 * S; k += 128)
        atomicAdd(&g_TR[b * (10 * S) + k], (&s_T[0][0][0])[k] + (&s_T[1][0][0])[k]);
}

// ---------------------------------------------------------------------------
// K2 (tail): halo-combine + both GEMVs + sigmoid + outer product + re-zero.
// Grid = 16 (one block per batch), 256 threads.
// ---------------------------------------------------------------------------
__global__ void __launch_bounds__(256) k_tail(const float* __restrict__ ww_lw,
                                              const float* __restrict__ ww_lb,
                                              const float* __restrict__ hw_lw,
                                              const float* __restrict__ hw_lb,
                                              float* __restrict__ out) {
    int b    = blockIdx.x;
    int t    = threadIdx.x;
    int warp = t >> 5, lane = t & 31;

    __shared__ float s_in[2 * S];           // ww_in [0:128], hw_in [128:256]
    __shared__ __align__(16) float s_ww[S];
    __shared__ float s_hw[S];

    float* TR = g_TR + b * (10 * S);

    // Halo combine: t<128 -> ww input w=t; t>=128 -> hw input h=t-128
    {
        int branch = t >> 7;                // 0 ww, 1 hw
        int o      = t & 127;
        const float* Tb = TR + branch * (5 * S);
        float acc = 0.f;
#pragma unroll
        for (int k5 = 0; k5 < 5; k5++) {
            int ip = o + k5 - 2;
            if (ip >= 0 && ip < S) acc += Tb[k5 * S + ip];
        }
        s_in[t] = acc;
    }
    __syncthreads();

    // GEMV: warps 0-3 -> ww outputs, warps 4-7 -> hw outputs.
    // Each warp: 32 outputs, lanes stride over k (coalesced weight rows).
    {
        int branch = warp >> 2;             // 0 ww, 1 hw
        int wsub   = warp & 3;
        const float* lw  = branch ? hw_lw : ww_lw;
        const float* lb  = branch ? hw_lb : ww_lb;
        const float* vin = s_in + branch * S;
        for (int j = wsub; j < S; j += 4) {
            const float* row = lw + j * S;
            float acc = 0.f;
#pragma unroll
            for (int kk = 0; kk < 4; kk++) {
                int k = lane + kk * 32;
                acc = fmaf(vin[k], __ldg(&row[k]), acc);
            }
#pragma unroll
            for (int off = 16; off > 0; off >>= 1)
                acc += __shfl_down_sync(0xFFFFFFFFu, acc, off);
            if (lane == 0) {
                acc += __ldg(&lb[j]);
                float sg = 1.f / (1.f + expf(-acc));
                if (branch == 0) s_ww[j] = sg;
                else             s_hw[j] = sg;
            }
        }
    }

    // Re-zero this batch's TR slice for the next kernel_launch call.
    for (int k = t; k < 10 * S; k += 256) TR[k] = 0.f;
    __syncthreads();

    // Outer product: out[b,h,w] = hw[h] * ww[w]; 4096 float4 / 256 threads.
    float4* o4 = reinterpret_cast<float4*>(out + (size_t)b * PLANE);
    const float4* wv4 = reinterpret_cast<const float4*>(s_ww);
#pragma unroll
    for (int it = 0; it < 16; it++) {
        int q  = t + it * 256;
        int h  = q >> 5;
        int w4 = q & 31;
        float hv = s_hw[h];
        float4 wv = wv4[w4];
        o4[q] = make_float4(hv * wv.x, hv * wv.y, hv * wv.z, hv * wv.w);
    }
}

// ---------------------------------------------------------------------------
extern "C" void kernel_launch(void* const* d_in, const int* in_sizes, int n_in,
                              void* d_out, int out_size) {
    const float* x      = (const float*)d_in[0];
    const float* w_conv = (const float*)d_in[1];
    const float* w_ww   = (const float*)d_in[2];
    const float* w_hw   = (const float*)d_in[3];
    const float* ww_lw  = (const float*)d_in[4];
    const float* ww_lb  = (const float*)d_in[5];
    const float* hw_lw  = (const float*)d_in[6];
    const float* hw_lb  = (const float*)d_in[7];
    float* out = (float*)d_out;

    k_conv_fused<<<2048, 128>>>(x, w_conv, w_ww, w_hw);
    k_tail<<<BATCH, 256>>>(ww_lw, ww_lb, hw_lw, hw_lb, out);
}